// round 7
// baseline (speedup 1.0000x reference)
#include <cuda_runtime.h>
#include <cstdint>

// MessagePassing: out[n] = sum over incident edges (n, other): r[other] * e[edge]
// (covers both directions of the reference's rij/rji scatter).
// Inputs: d_in[0]=r [50000,128] f32, d_in[1]=e [500000,128] f32,
//         d_in[2]=a [500000,2] int32. d_out: [50000,128] f32.
//
// Two-phase pull:
//  1) build: per edge, append (edge_id, other) into both endpoints' fixed-cap
//     incidence rows (atomicAdd slot counters; Poisson(20) degree, CAP=96 safe).
//  2) pull: warp per node, register accumulator, one plain 512B store.
// Removes the 512MB of RED traffic from the LTS-bound budget (costs +256MB of
// e reads): L2 bytes 1.28GB -> ~1.09GB. No output memset needed.

#define D_FEAT 128
#define NODES_MAX 50000
#define CAP 96

__device__ int  g_cnt[NODES_MAX];
__device__ int2 g_tab[(size_t)NODES_MAX * CAP];

__global__ __launch_bounds__(256)
void build_incidence(const int2* __restrict__ a, int n_edges) {
    int i = blockIdx.x * blockDim.x + threadIdx.x;
    if (i >= n_edges) return;
    int2 st = __ldg(a + i);
    int ss = atomicAdd(&g_cnt[st.x], 1);
    if (ss < CAP) g_tab[(size_t)st.x * CAP + ss] = make_int2(i, st.y);
    int tt = atomicAdd(&g_cnt[st.y], 1);
    if (tt < CAP) g_tab[(size_t)st.y * CAP + tt] = make_int2(i, st.x);
}

__global__ __launch_bounds__(256)
void pull_kernel(const float* __restrict__ r,
                 const float* __restrict__ e,
                 float* __restrict__ out,
                 int n_nodes) {
    int node = blockIdx.x * (blockDim.x >> 5) + (threadIdx.x >> 5);
    if (node >= n_nodes) return;
    int lane = threadIdx.x & 31;

    int cnt = g_cnt[node];
    if (cnt > CAP) cnt = CAP;

    const int2* row = g_tab + (size_t)node * CAP;

    float4 acc = make_float4(0.f, 0.f, 0.f, 0.f);

    // windowed entry prefetch: lane k holds entry (win + k); broadcast via shfl
    int2 ent = (lane < cnt) ? __ldg(row + lane) : make_int2(0, 0);

    for (int k = 0; k < cnt; k++) {
        int kk = k & 31;
        if (kk == 0 && k > 0) {
            int idx = k + lane;
            ent = (idx < cnt) ? __ldg(row + idx) : make_int2(0, 0);
        }
        int eid = __shfl_sync(0xffffffffu, ent.x, kk);
        int oth = __shfl_sync(0xffffffffu, ent.y, kk);

        float4 ev = __ldcs(reinterpret_cast<const float4*>(e + (long long)eid * D_FEAT) + lane);
        float4 rv = __ldg (reinterpret_cast<const float4*>(r + (long long)oth * D_FEAT) + lane);

        acc.x += ev.x * rv.x;
        acc.y += ev.y * rv.y;
        acc.z += ev.z * rv.z;
        acc.w += ev.w * rv.w;
    }

    reinterpret_cast<float4*>(out + (long long)node * D_FEAT)[lane] = acc;
}

extern "C" void kernel_launch(void* const* d_in, const int* in_sizes, int n_in,
                              void* d_out, int out_size) {
    const float* r = (const float*)d_in[0];
    const float* e = (const float*)d_in[1];
    const int2*  a = (const int2*)d_in[2];
    float*     out = (float*)d_out;

    int n_nodes = in_sizes[0] / D_FEAT;   // 50000
    int n_edges = in_sizes[1] / D_FEAT;   // 500000

    // zero the per-node slot counters (scratch lives in __device__ globals)
    void* cnt_ptr = nullptr;
    cudaGetSymbolAddress(&cnt_ptr, g_cnt);
    cudaMemsetAsync(cnt_ptr, 0, (size_t)n_nodes * sizeof(int), 0);

    int bblocks = (n_edges + 255) / 256;
    build_incidence<<<bblocks, 256>>>(a, n_edges);

    int warps_per_block = 8;
    int pblocks = (n_nodes + warps_per_block - 1) / warps_per_block;
    pull_kernel<<<pblocks, warps_per_block * 32>>>(r, e, out, n_nodes);
}

// round 9
// speedup vs baseline: 1.1621x; 1.1621x over previous
#include <cuda_runtime.h>
#include <cstdint>

// MessagePassing: out[t] += r[s]*e ; out[s] += r[t]*e  per edge (s,t)
// Inputs: d_in[0]=r [50000,128] f32, d_in[1]=e [500000,128] f32,
//         d_in[2]=a [500000,2] int32. d_out: [50000,128] f32.
//
// Half-pull hybrid. Build: incidence list bucketed by SOURCE only: per node s,
// records (eid, t). Compute: warp per node n:
//   acc      += r[t] * e[eid]      (pull side -> registers, ONE RED per node)
//   out[t]   += r[n] * e[eid]      (push side; r[n] register-resident)
// LTS bytes drop 1.28GB -> ~0.87GB (removes per-edge RED for one direction and
// the r[s] gather). e is read once, randomly ordered (~50us DRAM, sub-binding).
//
// (Resubmission of R8 — previous round died to a broker/container infra
// failure before producing any measurement.)

#define D_FEAT 128
#define NODES_MAX 50000
#define CAP 64                      // out-degree ~ Poisson(10); P(>64) ~ 1e-40

__device__ int  g_cnt[NODES_MAX];
__device__ int2 g_tab[(size_t)NODES_MAX * CAP];   // (eid, t) records, 25.6MB

__device__ __forceinline__ void red_add_v4(float* addr, float4 v) {
    asm volatile("red.global.add.v4.f32 [%0], {%1,%2,%3,%4};"
                 :: "l"(addr), "f"(v.x), "f"(v.y), "f"(v.z), "f"(v.w)
                 : "memory");
}

__global__ __launch_bounds__(256)
void build_src_list(const int2* __restrict__ a, int n_edges) {
    int i = blockIdx.x * blockDim.x + threadIdx.x;
    if (i >= n_edges) return;
    int2 st = __ldg(a + i);
    int slot = atomicAdd(&g_cnt[st.x], 1);
    if (slot < CAP) g_tab[(size_t)st.x * CAP + slot] = make_int2(i, st.y);
}

__global__ __launch_bounds__(256)
void halfpull_kernel(const float* __restrict__ r,
                     const float* __restrict__ e,
                     float* __restrict__ out,
                     int n_nodes) {
    int node = blockIdx.x * (blockDim.x >> 5) + (threadIdx.x >> 5);
    if (node >= n_nodes) return;
    int lane = threadIdx.x & 31;

    int cnt = g_cnt[node];
    if (cnt > CAP) cnt = CAP;

    // this node's own features, reused for every push-side message
    float4 rn = __ldg(reinterpret_cast<const float4*>(r + (long long)node * D_FEAT) + lane);

    float4 acc = make_float4(0.f, 0.f, 0.f, 0.f);

    const int2* row = g_tab + (size_t)node * CAP;
    // windowed record prefetch: lane k holds record (win + k); broadcast via shfl
    int2 ent = (lane < cnt) ? __ldg(row + lane) : make_int2(0, 0);

    for (int k = 0; k < cnt; k++) {
        int kk = k & 31;
        if (kk == 0 && k > 0) {
            int idx = k + lane;
            ent = (idx < cnt) ? __ldg(row + idx) : make_int2(0, 0);
        }
        int eid = __shfl_sync(0xffffffffu, ent.x, kk);
        int t   = __shfl_sync(0xffffffffu, ent.y, kk);

        float4 ev = __ldcs(reinterpret_cast<const float4*>(e + (long long)eid * D_FEAT) + lane);
        float4 rt = __ldg (reinterpret_cast<const float4*>(r + (long long)t   * D_FEAT) + lane);

        // pull side: message t -> node (r[t] * e)
        acc.x += rt.x * ev.x;
        acc.y += rt.y * ev.y;
        acc.z += rt.z * ev.z;
        acc.w += rt.w * ev.w;

        // push side: message node -> t (r[node] * e)
        red_add_v4(out + (long long)t * D_FEAT + lane * 4,
                   make_float4(rn.x * ev.x, rn.y * ev.y, rn.z * ev.z, rn.w * ev.w));
    }

    // single RED deposits the whole pull-side sum (out also receives push REDs
    // from other warps, so a plain store is not allowed)
    red_add_v4(out + (long long)node * D_FEAT + lane * 4, acc);
}

extern "C" void kernel_launch(void* const* d_in, const int* in_sizes, int n_in,
                              void* d_out, int out_size) {
    const float* r = (const float*)d_in[0];
    const float* e = (const float*)d_in[1];
    const int2*  a = (const int2*)d_in[2];
    float*     out = (float*)d_out;

    int n_nodes = in_sizes[0] / D_FEAT;   // 50000
    int n_edges = in_sizes[1] / D_FEAT;   // 500000

    // zero output (poisoned) and the per-node slot counters
    cudaMemsetAsync(d_out, 0, (size_t)out_size * sizeof(float), 0);
    void* cnt_ptr = nullptr;
    cudaGetSymbolAddress(&cnt_ptr, g_cnt);
    cudaMemsetAsync(cnt_ptr, 0, (size_t)n_nodes * sizeof(int), 0);

    int bblocks = (n_edges + 255) / 256;
    build_src_list<<<bblocks, 256>>>(a, n_edges);

    int warps_per_block = 8;
    int pblocks = (n_nodes + warps_per_block - 1) / warps_per_block;
    halfpull_kernel<<<pblocks, warps_per_block * 32>>>(r, e, out, n_nodes);
}